// round 12
// baseline (speedup 1.0000x reference)
#include <cuda_runtime.h>
#include <cstdint>

// Problem constants
static constexpr int Bn   = 2;
static constexpr int Din  = 18;
static constexpr int Dout = 16;
static constexpr int Hn   = 128;
static constexpr int Wn   = 128;
static constexpr int TPB  = 32;                   // ONE warp per CTA (persistent)
static constexpr int ROWF = 125;                  // floats per voxel row (5^3)
static constexpr int TILE_VOX   = 32;             // voxels per tile = lanes
static constexpr int TILE_WORDS = TILE_VOX * ROWF;        // 4000 floats
static constexpr int TILE_BYTES = TILE_WORDS * 4;         // 16000 B
static constexpr int NTILES = (Bn * Dout * Hn * Wn) / TILE_VOX;  // 16384
static constexpr int NCTA   = 148 * 7;            // persistent grid = 1036
static constexpr int SMEM_BYTES = 2 * TILE_BYTES + 16;    // dom + gui + 2 mbarriers

// ---------------- TMA bulk + mbarrier helpers ----------------
__device__ __forceinline__ void mbar_init1(uint32_t mbar) {
    asm volatile("mbarrier.init.shared.b64 [%0], 1;" :: "r"(mbar) : "memory");
}
__device__ __forceinline__ void fence_proxy_async_cta() {
    asm volatile("fence.proxy.async.shared::cta;" ::: "memory");
}
__device__ __forceinline__ void bulk_copy(uint32_t sdst, const void* gsrc,
                                          uint32_t bytes, uint32_t mbar) {
    asm volatile("mbarrier.arrive.expect_tx.shared.b64 _, [%0], %1;"
                 :: "r"(mbar), "r"(bytes) : "memory");
    asm volatile("cp.async.bulk.shared::cta.global.mbarrier::complete_tx::bytes "
                 "[%0], [%1], %2, [%3];"
                 :: "r"(sdst), "l"(gsrc), "r"(bytes), "r"(mbar) : "memory");
}
__device__ __forceinline__ void mbar_wait(uint32_t mbar, uint32_t parity) {
    asm volatile(
        "{\n\t"
        ".reg .pred P;\n\t"
        "WAIT_%=:\n\t"
        "mbarrier.try_wait.parity.acquire.cta.shared::cta.b64 P, [%0], %1, 0x989680;\n\t"
        "@P bra WAIT_DONE_%=;\n\t"
        "bra WAIT_%=;\n\t"
        "WAIT_DONE_%=:\n\t"
        "}"
        :: "r"(mbar), "r"(parity) : "memory");
}

// Full 5^3 -> 3^3 valid cross-correlation, input-stationary.
// 125 LDS.32 (conflict-free: lane word-stride 125 is odd) + 729 FMA.
__device__ __forceinline__ void conv_acc(const float* __restrict__ s,
                                         const float (&wk)[27], float (&acc)[27]) {
#pragma unroll
    for (int p = 0; p < 5; p++)
#pragma unroll
    for (int q = 0; q < 5; q++)
#pragma unroll
    for (int r = 0; r < 5; r++) {
        float v = s[p * 25 + q * 5 + r];
#pragma unroll
        for (int a = 0; a < 3; a++) {
            if (p - a < 0 || p - a > 2) continue;
#pragma unroll
            for (int bq = 0; bq < 3; bq++) {
                if (q - bq < 0 || q - bq > 2) continue;
#pragma unroll
                for (int cr = 0; cr < 3; cr++) {
                    if (r - cr < 0 || r - cr > 2) continue;
                    acc[(a * 3 + bq) * 3 + cr] =
                        fmaf(v, wk[((p - a) * 3 + (q - bq)) * 3 + (r - cr)],
                             acc[(a * 3 + bq) * 3 + cr]);
                }
            }
        }
    }
}

__global__ void __launch_bounds__(TPB, 7)
jbf_kernel(const float* __restrict__ x,
           const float* __restrict__ dom,
           const float* __restrict__ gui,
           const float* __restrict__ dom_w,
           const float* __restrict__ dom_b,
           const float* __restrict__ rng_w,
           const float* __restrict__ rng_b,
           float* __restrict__ out)
{
    extern __shared__ float sbuf[];
    // words: [0,4000) dom tile, [4000,8000) gui tile, then 2 mbarriers

    const int lane = threadIdx.x;
    const int bid  = blockIdx.x;

    const uint32_t sm32   = (uint32_t)__cvta_generic_to_shared(sbuf);
    const uint32_t s_dom  = sm32;
    const uint32_t s_gui  = sm32 + (uint32_t)TILE_BYTES;
    const uint32_t mb_dom = sm32 + 2u * TILE_BYTES;
    const uint32_t mb_gui = mb_dom + 8u;
    const float* srow_dom = sbuf + lane * ROWF;
    const float* srow_gui = sbuf + TILE_WORDS + lane * ROWF;

    // ---- Persistent-warp prologue: mbarriers + first tile's copies ----
    if (lane == 0) {
        mbar_init1(mb_dom);
        mbar_init1(mb_gui);
        fence_proxy_async_cta();
        bulk_copy(s_dom, dom + (long long)bid * TILE_WORDS, TILE_BYTES, mb_dom);
        bulk_copy(s_gui, gui + (long long)bid * TILE_WORDS, TILE_BYTES, mb_gui);
    }
    __syncwarp();

    // Hoist both weight sets + biases into registers (constant across tiles).
    float wkd[27], wkr[27];
#pragma unroll
    for (int t = 0; t < 27; t++) wkd[t] = dom_w[t];
#pragma unroll
    for (int t = 0; t < 27; t++) wkr[t] = rng_w[t];
    const float db = dom_b[0];
    const float rb = rng_b[0];

    uint32_t parity = 0;

    for (int t = bid; t < NTILES; t += NCTA) {
        const long long m = (long long)t * TILE_VOX + lane;  // this lane's voxel
        const int w = (int)(m & (Wn - 1));
        const int h = (int)((m >> 7) & (Hn - 1));
        const int d = (int)((m >> 14) & (Dout - 1));
        const int b = (int)(m >> 18);
        const int tn = t + NCTA;                             // next tile (prefetch)

        // ---- Phase 1: domain conv ----
        mbar_wait(mb_dom, parity);

        float dk[27];
#pragma unroll
        for (int o = 0; o < 27; o++) dk[o] = 0.0f;
        conv_acc(srow_dom, wkd, dk);

        // dom buffer free -> prefetch next tile's dom (overlaps conv2+epilogue)
        __syncwarp();
        fence_proxy_async_cta();
        if (lane == 0 && tn < NTILES)
            bulk_copy(s_dom, dom + (long long)tn * TILE_WORDS, TILE_BYTES, mb_dom);

        // ---- Phase 2: range conv ----
        mbar_wait(mb_gui, parity);

        float rk[27];
#pragma unroll
        for (int o = 0; o < 27; o++) rk[o] = 0.0f;
        conv_acc(srow_gui, wkr, rk);

        // gui buffer free -> prefetch next tile's gui (overlaps epilogue+conv1)
        __syncwarp();
        fence_proxy_async_cta();
        if (lane == 0 && tn < NTILES)
            bulk_copy(s_gui, gui + (long long)tn * TILE_WORDS, TILE_BYTES, mb_gui);

        // ---- Fused epilogue: ReLU, bilateral weight, weighted x-sum ----
        float num = 0.0f, den = 0.0f;
#pragma unroll
        for (int i = 0; i < 3; i++)
#pragma unroll
        for (int j = 0; j < 3; j++) {
            const int hh = h + j - 1;
            const bool hok = (hh >= 0) && (hh < Hn);
            const long long base = (((long long)b * Din + (d + i)) << 14) + (hh << 7);
#pragma unroll
            for (int l = 0; l < 3; l++) {
                const int o = (i * 3 + j) * 3 + l;
                float dko = fmaxf(dk[o] + db, 0.0f);
                float rko = fmaxf(rk[o] + rb, 0.0f);
                float wt  = fmaf(dko, rko, 1e-10f);
                const int ww = w + l - 1;
                float xv = (hok && ww >= 0 && ww < Wn) ? x[base + ww] : 0.0f;
                num = fmaf(wt, xv, num);
                den += wt;
            }
        }

        out[m] = num / den;
        parity ^= 1u;
    }
}

extern "C" void kernel_launch(void* const* d_in, const int* in_sizes, int n_in,
                              void* d_out, int out_size) {
    const float* x     = (const float*)d_in[0];
    const float* dom   = (const float*)d_in[1];
    const float* gui   = (const float*)d_in[2];
    const float* dom_w = (const float*)d_in[3];
    const float* dom_b = (const float*)d_in[4];
    const float* rng_w = (const float*)d_in[5];
    const float* rng_b = (const float*)d_in[6];
    float* out = (float*)d_out;

    cudaFuncSetAttribute(jbf_kernel, cudaFuncAttributeMaxDynamicSharedMemorySize,
                         SMEM_BYTES);

    jbf_kernel<<<NCTA, TPB, SMEM_BYTES>>>(x, dom, gui, dom_w, dom_b, rng_w, rng_b, out);
}